// round 16
// baseline (speedup 1.0000x reference)
#include <cuda_runtime.h>
#include <cuda_bf16.h>
#include <cstdint>

#define B_ 8
#define T_ 2048
#define H_ 64
#define M_ 32
#define S_ 20
#define E_ 3
#define IN_ 32
#define EPS_ 1e-8f
#define LOG2E_ 1.4426950408889634f

#define TQ_ 64           // q rows per CTA
#define TK_ 64           // keys per smem tile
#define NKT_ (T_ / TK_)  // 32

// ---------------- scratch (no cudaMalloc allowed) ----------------
__device__ __align__(16) float g_mhat[B_ * T_ * M_];
// Q,K rows: 8 blocks of 16B, block g=(kc*4+r) = [hi(8kc+r), hi(8kc+r+4), lo(8kc+r), lo(8kc+r+4)]
__device__ __align__(16) unsigned int g_Qs[E_ * B_ * T_ * 32];
__device__ __align__(16) unsigned int g_Ks[E_ * B_ * T_ * 32];
// V transposed, fragment-interleaved: row m = T_ words; tile kt at words kt*64,
// 16 blocks of 16B: block g=(kc*4+r) = [hi(8kc+r), hi(8kc+r+4), lo(8kc+r), lo(8kc+r+4)] (t-pair idx)
__device__ __align__(16) unsigned int g_Vt[E_ * B_ * 32 * T_];

// ---------------- helpers ----------------
static __device__ __forceinline__ float ex2f(float x) {
    float r; asm("ex2.approx.ftz.f32 %0, %1;" : "=f"(r) : "f"(x)); return r;
}
static __device__ __forceinline__ unsigned short f2bf(float f) {
    __nv_bfloat16 h = __float2bfloat16(f);
    return *reinterpret_cast<unsigned short*>(&h);
}
static __device__ __forceinline__ float bf2f(unsigned short u) {
    __nv_bfloat16 h; *reinterpret_cast<unsigned short*>(&h) = u;
    return __bfloat162float(h);
}
static __device__ __forceinline__ unsigned int pack2(float hi, float lo) {
    unsigned int d;
    asm("cvt.rn.bf16x2.f32 %0, %1, %2;" : "=r"(d) : "f"(hi), "f"(lo));
    return d;
}
static __device__ __forceinline__ float unpk_lo(unsigned int v) { return __uint_as_float(v << 16); }
static __device__ __forceinline__ float unpk_hi(unsigned int v) { return __uint_as_float(v & 0xffff0000u); }

static __device__ __forceinline__ unsigned long long pk2(float a, float b) {
    unsigned long long r;
    asm("mov.b64 %0, {%1, %2};" : "=l"(r) : "r"(__float_as_uint(a)), "r"(__float_as_uint(b)));
    return r;
}
static __device__ __forceinline__ void upk2(unsigned long long v, float& a, float& b) {
    unsigned lo, hi;
    asm("mov.b64 {%0, %1}, %2;" : "=r"(lo), "=r"(hi) : "l"(v));
    a = __uint_as_float(lo); b = __uint_as_float(hi);
}
static __device__ __forceinline__ unsigned long long ffma2(
        unsigned long long a, unsigned long long b, unsigned long long c) {
    unsigned long long d;
    asm("fma.rn.f32x2 %0, %1, %2, %3;" : "=l"(d) : "l"(a), "l"(b), "l"(c));
    return d;
}

static __device__ __forceinline__ void mma16816(
        float* c, unsigned int a0, unsigned int a1, unsigned int a2, unsigned int a3,
        unsigned int b0, unsigned int b1) {
    asm volatile(
        "mma.sync.aligned.m16n8k16.row.col.f32.bf16.bf16.f32 "
        "{%0,%1,%2,%3}, {%4,%5,%6,%7}, {%8,%9}, {%0,%1,%2,%3};"
        : "+f"(c[0]), "+f"(c[1]), "+f"(c[2]), "+f"(c[3])
        : "r"(a0), "r"(a1), "r"(a2), "r"(a3), "r"(b0), "r"(b1));
}

static __device__ __forceinline__ uint32_t smem_u32(const void* p) {
    uint32_t a;
    asm("{ .reg .u64 t; cvta.to.shared.u64 t, %1; cvt.u32.u64 %0, t; }" : "=r"(a) : "l"(p));
    return a;
}
static __device__ __forceinline__ void cpa16(uint32_t s, const void* g) {
    asm volatile("cp.async.cg.shared.global [%0], [%1], 16;" :: "r"(s), "l"(g));
}
#define CPA_COMMIT() asm volatile("cp.async.commit_group;" ::: "memory")
#define CPA_WAIT0()  asm volatile("cp.async.wait_group 0;" ::: "memory")

// ---------------- prep kernel: qkv (z=0..2) + mem (z=3) ----------------
// fragment-interleaved pack: word i (0..15) -> block g=(i>>3)*4+(i&3), slot (i>>2)&1
static __device__ __forceinline__ void split_pack_row(const float* a, unsigned int* dst) {
#pragma unroll
    for (int i = 0; i < 16; i++) {
        int ph = ((i >> 3) * 4 + (i & 3)) * 4 + ((i >> 2) & 1);
        unsigned short h0 = f2bf(a[2 * i]), h1 = f2bf(a[2 * i + 1]);
        dst[ph] = (unsigned)h0 | ((unsigned)h1 << 16);
        float l0 = a[2 * i] - bf2f(h0), l1 = a[2 * i + 1] - bf2f(h1);
        dst[ph + 2] = (unsigned)f2bf(l0) | ((unsigned)f2bf(l1) << 16);
    }
}

__global__ __launch_bounds__(128) void prep_kernel(
        const float* __restrict__ x,
        const float* __restrict__ memory,
        const float* __restrict__ iq,
        const float* __restrict__ hidden,
        const float* __restrict__ Wq,
        const float* __restrict__ Wk,
        const float* __restrict__ Wv) {
    __shared__ unsigned long long w2[3][H_ * 16];   // qkv: packed weight pairs (24KB)
    __shared__ float sv[128 * 32];                  // qkv: V rows for transpose (16KB)
    int tid = threadIdx.x;

    if (blockIdx.z == 3) {
        // ================= mem path: thread per (b,t) row =================
        float* iqs = (float*)w2[0];                // IN*M floats
        float* smem_m = (float*)w2[0] + IN_ * M_;  // S*M floats
        for (int n = tid; n < IN_ * M_; n += 128) iqs[n] = iq[n];
        for (int n = tid; n < S_ * M_; n += 128) smem_m[n] = memory[n];
        __syncthreads();

        int bt = (blockIdx.y * 16 + blockIdx.x) * 128 + tid;   // 0..16383
        float xr[IN_];
        const float4* x4 = (const float4*)(x + (size_t)bt * IN_);
#pragma unroll
        for (int i = 0; i < IN_ / 4; i++) {
            float4 v = x4[i];
            xr[4 * i] = v.x; xr[4 * i + 1] = v.y; xr[4 * i + 2] = v.z; xr[4 * i + 3] = v.w;
        }
        float qv[M_];
#pragma unroll
        for (int m = 0; m < M_; m++) qv[m] = 0.f;
#pragma unroll
        for (int i = 0; i < IN_; i++) {
            float xv = xr[i];
#pragma unroll
            for (int m = 0; m < M_; m++) qv[m] = fmaf(xv, iqs[i * M_ + m], qv[m]);
        }
        float s[S_];
        float mx = -3e38f;
#pragma unroll
        for (int j = 0; j < S_; j++) {
            float d0 = 0.f, d1 = 0.f, d2 = 0.f, d3 = 0.f;
            const float* r = smem_m + j * M_;
#pragma unroll
            for (int m = 0; m < M_; m += 4) {
                d0 = fmaf(qv[m], r[m], d0);
                d1 = fmaf(qv[m + 1], r[m + 1], d1);
                d2 = fmaf(qv[m + 2], r[m + 2], d2);
                d3 = fmaf(qv[m + 3], r[m + 3], d3);
            }
            s[j] = (d0 + d1) + (d2 + d3);
            mx = fmaxf(mx, s[j]);
        }
        float L = 0.f;
#pragma unroll
        for (int j = 0; j < S_; j++) {
            s[j] = ex2f((s[j] - mx) * LOG2E_);
            L += s[j];
        }
        float macc[M_];
#pragma unroll
        for (int m = 0; m < M_; m++) macc[m] = 0.f;
#pragma unroll
        for (int j = 0; j < S_; j++) {
            float p = s[j];
            const float* r = smem_m + j * M_;
#pragma unroll
            for (int m = 0; m < M_; m++) macc[m] = fmaf(p, r[m], macc[m]);
        }
        float invL = 1.0f / L;
        float ss = 0.f;
#pragma unroll
        for (int m = 0; m < M_; m++) {
            macc[m] *= invL;
            ss += macc[m] * macc[m];
        }
        float rinv = 1.0f / fmaxf(sqrtf(ss), EPS_);
        float4* o4 = (float4*)(g_mhat + (size_t)bt * M_);
#pragma unroll
        for (int i = 0; i < M_ / 4; i++) {
            float4 v;
            v.x = macc[4 * i] * rinv; v.y = macc[4 * i + 1] * rinv;
            v.z = macc[4 * i + 2] * rinv; v.w = macc[4 * i + 3] * rinv;
            o4[i] = v;
        }
        return;
    }

    // ================= qkv path =================
    int e = blockIdx.z, b = blockIdx.y;
    const float* Ws[3] = {Wq, Wk, Wv};
    for (int p = 0; p < 3; p++) {
        const unsigned long long* src = (const unsigned long long*)(Ws[p] + e * H_ * M_);
        for (int n = tid; n < H_ * 16; n += 128) w2[p][n] = src[n];
    }
    __syncthreads();

    int t0 = blockIdx.x * 128;
    int t = t0 + tid;
    size_t row = (size_t)(e * B_ + b) * T_ + t;
    float h[H_];
    const float4* h4 = (const float4*)(hidden + row * H_);
#pragma unroll
    for (int i = 0; i < H_ / 4; i++) {
        float4 v = h4[i];
        h[4 * i] = v.x; h[4 * i + 1] = v.y; h[4 * i + 2] = v.z; h[4 * i + 3] = v.w;
    }
    for (int p = 0; p < 3; p++) {
        unsigned long long acc2[16];
#pragma unroll
        for (int m = 0; m < 16; m++) acc2[m] = 0ull;
#pragma unroll
        for (int i = 0; i < H_; i++) {
            unsigned long long h2 = pk2(h[i], h[i]);
#pragma unroll
            for (int m = 0; m < 16; m++)
                acc2[m] = ffma2(h2, w2[p][i * 16 + m], acc2[m]);
        }
        float acc[M_];
#pragma unroll
        for (int m = 0; m < 16; m++) upk2(acc2[m], acc[2 * m], acc[2 * m + 1]);

        if (p == 0) {
#pragma unroll
            for (int m = 0; m < M_; m++) acc[m] *= LOG2E_;   // log2-domain scores
            unsigned int pk[32];
            split_pack_row(acc, pk);
            uint4* o = (uint4*)(g_Qs + row * 32);
#pragma unroll
            for (int i = 0; i < 8; i++) o[i] = ((uint4*)pk)[i];
        } else if (p == 1) {
            unsigned int pk[32];
            split_pack_row(acc, pk);
            uint4* o = (uint4*)(g_Ks + row * 32);
#pragma unroll
            for (int i = 0; i < 8; i++) o[i] = ((uint4*)pk)[i];
        } else {
#pragma unroll
            for (int m = 0; m < M_; m++) sv[tid * 32 + m] = acc[m];
        }
    }
    __syncthreads();
    // transpose V: thread owns (m, t-chunk of 32); fragment-interleaved write
    int m = tid & 31, tc = tid >> 5;
    int tstart = t0 + tc * 32;
    int tile = tstart >> 6;            // key-tile index
    int c2 = (tstart >> 5) & 1;        // 32-t chunk within tile
    unsigned int* dstv = g_Vt + ((size_t)(e * B_ + b) * 32 + m) * T_ + (size_t)tile * 64;
#pragma unroll
    for (int j = 0; j < 16; j++) {
        int P = c2 * 16 + j;           // t-pair index within tile (0..31)
        int ph = ((P >> 3) * 4 + (P & 3)) * 4 + ((P >> 2) & 1);
        float f0 = sv[(tc * 32 + 2 * j) * 32 + m];
        float f1 = sv[(tc * 32 + 2 * j + 1) * 32 + m];
        unsigned short h0 = f2bf(f0), h1 = f2bf(f1);
        dstv[ph] = (unsigned)h0 | ((unsigned)h1 << 16);
        float l0 = f0 - bf2f(h0), l1 = f1 - bf2f(h1);
        dstv[ph + 2] = (unsigned)f2bf(l0) | ((unsigned)f2bf(l1) << 16);
    }
}

// ---------------- kernel C: HMMA flash attention + fused cosine ----------------
#define KST_ 176      // 64 rows x (128B data + pad)
#define VST_ 288      // 32 rows x (256B data + pad)

__global__ __launch_bounds__(128, 5) void attn_kernel(float* __restrict__ out) {
    __shared__ __align__(16) char Ksm[2][TK_ * KST_];      // 22KB
    __shared__ __align__(16) char Vsm[2][32 * VST_];       // 18KB

    int tid = threadIdx.x, wid = tid >> 5, lane = tid & 31;
    int e = blockIdx.z, b = blockIdx.y;
    int qbase = blockIdx.x * TQ_;
    size_t eb = (size_t)(e * B_ + b);
    int lq = lane >> 2;      // 0..7
    int lr = lane & 3;       // 0..3

    const uint4* kg = (const uint4*)g_Ks + eb * T_ * 8;
    const uint4* vg = (const uint4*)g_Vt + eb * 32 * (T_ / 4);   // 512 uint4 per row

    uint32_t ksb[2] = {smem_u32(Ksm[0]), smem_u32(Ksm[1])};
    uint32_t vsb[2] = {smem_u32(Vsm[0]), smem_u32(Vsm[1])};

    // ---- prefetch tile 0 via cp.async ----
    {
#pragma unroll
        for (int j = 0; j < 4; j++) {
            int i = tid + j * 128;
            int r = i >> 3, ch = i & 7;
            cpa16(ksb[0] + r * KST_ + ch * 16, kg + (size_t)r * 8 + ch);
        }
#pragma unroll
        for (int j = 0; j < 4; j++) {
            int i = tid + j * 128;
            int m = i >> 4, ch = i & 15;
            cpa16(vsb[0] + m * VST_ + ch * 16, vg + (size_t)m * 512 + ch);
        }
        CPA_COMMIT();
    }

    // ---- persistent Q A-fragments: direct LDG.128 (fragment-interleaved rows) ----
    unsigned int qhi[2][4], qlo[2][4];
    {
        int r0 = wid * 16 + lq;
        const uint4* q0 = (const uint4*)(g_Qs + (eb * T_ + qbase + r0) * 32);
        const uint4* q1 = (const uint4*)(g_Qs + (eb * T_ + qbase + r0 + 8) * 32);
#pragma unroll
        for (int kc = 0; kc < 2; kc++) {
            uint4 A = q0[kc * 4 + lr];
            uint4 Bv = q1[kc * 4 + lr];
            qhi[kc][0] = A.x; qhi[kc][1] = Bv.x; qhi[kc][2] = A.y; qhi[kc][3] = Bv.y;
            qlo[kc][0] = A.z; qlo[kc][1] = Bv.z; qlo[kc][2] = A.w; qlo[kc][3] = Bv.w;
        }
    }

    float o[4][4];
#pragma unroll
    for (int i = 0; i < 4; i++)
#pragma unroll
        for (int j = 0; j < 4; j++) o[i][j] = 0.f;
    float m0 = -1e30f, m1 = -1e30f;

    for (int kt = 0; kt < NKT_; kt++) {
        int st = kt & 1;
        CPA_WAIT0();
        __syncthreads();
        // ---- prefetch next tile into other buffer ----
        if (kt + 1 < NKT_) {
            int ns = st ^ 1;
            int nk = kt + 1;
#pragma unroll
            for (int j = 0; j < 4; j++) {
                int i = tid + j * 128;
                int r = i >> 3, ch = i & 7;
                cpa16(ksb[ns] + r * KST_ + ch * 16, kg + (size_t)(nk * TK_ + r) * 8 + ch);
            }
#pragma unroll
            for (int j = 0; j < 4; j++) {
                int i = tid + j * 128;
                int m = i >> 4, ch = i & 15;
                cpa16(vsb[ns] + m * VST_ + ch * 16, vg + (size_t)m * 512 + nk * 16 + ch);
            }
            CPA_COMMIT();
        }

        // ---- S = Q K^T (split bf16, 3 passes); one LDS.128 per fragment ----
        float sc[8][4];
#pragma unroll
        for (int n = 0; n < 8; n++) {
            sc[n][0] = sc[n][1] = sc[n][2] = sc[n][3] = 0.f;
            const char* rowp = Ksm[st] + (n * 8 + lq) * KST_;
#pragma unroll
            for (int kc = 0; kc < 2; kc++) {
                uint4 kb = *(const uint4*)(rowp + (kc * 4 + lr) * 16);
                mma16816(sc[n], qhi[kc][0], qhi[kc][1], qhi[kc][2], qhi[kc][3], kb.x, kb.y);
                mma16816(sc[n], qlo[kc][0], qlo[kc][1], qlo[kc][2], qlo[kc][3], kb.x, kb.y);
                mma16816(sc[n], qhi[kc][0], qhi[kc][1], qhi[kc][2], qhi[kc][3], kb.z, kb.w);
            }
        }

        // ---- online max (log2 domain); rescale only when a row max advances ----
        float mt0 = -1e30f, mt1 = -1e30f;
#pragma unroll
        for (int n = 0; n < 8; n++) {
            mt0 = fmaxf(mt0, fmaxf(sc[n][0], sc[n][1]));
            mt1 = fmaxf(mt1, fmaxf(sc[n][2], sc[n][3]));
        }
        mt0 = fmaxf(mt0, __shfl_xor_sync(0xffffffffu, mt0, 1));
        mt0 = fmaxf(mt0, __shfl_xor_sync(0xffffffffu, mt0, 2));
        mt1 = fmaxf(mt1, __shfl_xor_sync(0xffffffffu, mt1, 1));
        mt1 = fmaxf(mt1, __shfl_xor_sync(0xffffffffu, mt1, 2));
        if (__any_sync(0xffffffffu, (mt0 > m0) || (mt1 > m1))) {
            float mn0 = fmaxf(m0, mt0), mn1 = fmaxf(m1, mt1);
            float s0 = ex2f(m0 - mn0), s1 = ex2f(m1 - mn1);
            m0 = mn0; m1 = mn1;
#pragma unroll
            for (int nv = 0; nv < 4; nv++) {
                o[nv][0] *= s0; o[nv][1] *= s0;
                o[nv][2] *= s1; o[nv][3] *= s1;
            }
        }

        // ---- P = ex2(S-m) -> A-frags; O += P V (split, 3 passes) ----
#pragma unroll
        for (int kc = 0; kc < 4; kc++) {
            float p00 = ex2f(sc[2 * kc][0] - m0), p01 = ex2f(sc[2 * kc][1] - m0);
            float p02 = ex2f(sc[2 * kc][2] - m1), p03 = ex2f(sc[2 * kc][3] - m1);
            float p10 = ex2f(sc[2 * kc + 1][0] - m0), p11 = ex2f(sc[2 * kc + 1][1] - m0);
            float p12 = ex2f(sc[2 * kc + 1][2] - m1), p13 = ex2f(sc[2 * kc + 1][3] - m1);
            unsigned int a0 = pack2(p01, p00);
            unsigned int a1 = pack2(p03, p02);
            unsigned int a2 = pack2(p11, p10);
            unsigned int a3 = pack2(p13, p12);
            unsigned int a0l = pack2(p01 - unpk_hi(a0), p00 - unpk_lo(a0));
            unsigned int a1l = pack2(p03 - unpk_hi(a1), p02 - unpk_lo(a1));
            unsigned int a2l = pack2(p11 - unpk_hi(a2), p10 - unpk_lo(a2));
            unsigned int a3l = pack2(p13 - unpk_hi(a3), p12 - unpk_lo(a3));
#pragma unroll
            for (int nv = 0; nv < 4; nv++) {
                const char* vrow = Vsm[st] + (nv * 8 + lq) * VST_;
                uint4 vb = *(const uint4*)(vrow + (kc * 4 + lr) * 16);
                mma16816(o[nv], a0, a1, a2, a3, vb.x, vb.y);
                mma16816(o[nv], a0l, a1l, a2l, a3l, vb.x, vb.y);
                mma16816(o[nv], a0, a1, a2, a3, vb.z, vb.w);
            }
        }
    }

    // ---- epilogue: cosine(o_row, mhat_row); softmax 1/l cancels in cosine ----
    int trow0 = qbase + wid * 16 + lq;
    int trow1 = trow0 + 8;
    float n20 = 0.f, dt0 = 0.f, n21 = 0.f, dt1 = 0.f;
    const float* mh0 = g_mhat + ((size_t)b * T_ + trow0) * M_;
    const float* mh1 = g_mhat + ((size_t)b * T_ + trow1) * M_;
#pragma unroll
    for (int nv = 0; nv < 4; nv++) {
        int col = nv * 8 + lr * 2;
        float2 w0 = *(const float2*)(mh0 + col);
        float2 w1 = *(const float2*)(mh1 + col);
        n20 += o[nv][0] * o[nv][0] + o[nv][1] * o[nv][1];
        dt0 += o[nv][0] * w0.x + o[nv][1] * w0.y;
        n21 += o[nv][2] * o[nv][2] + o[nv][3] * o[nv][3];
        dt1 += o[nv][2] * w1.x + o[nv][3] * w1.y;
    }
    n20 += __shfl_xor_sync(0xffffffffu, n20, 1);
    dt0 += __shfl_xor_sync(0xffffffffu, dt0, 1);
    n21 += __shfl_xor_sync(0xffffffffu, n21, 1);
    dt1 += __shfl_xor_sync(0xffffffffu, dt1, 1);
    n20 += __shfl_xor_sync(0xffffffffu, n20, 2);
    dt0 += __shfl_xor_sync(0xffffffffu, dt0, 2);
    n21 += __shfl_xor_sync(0xffffffffu, n21, 2);
    dt1 += __shfl_xor_sync(0xffffffffu, dt1, 2);
    if (lr == 0) {
        out[((size_t)b * T_ + trow0) * E_ + e] = dt0 / fmaxf(sqrtf(n20), EPS_);
        out[((size_t)b * T_ + trow1) * E_ + e] = dt1 / fmaxf(sqrtf(n21), EPS_);
    }
}

// ---------------- launch ----------------
extern "C" void kernel_launch(void* const* d_in, const int* in_sizes, int n_in,
                              void* d_out, int out_size) {
    const float* x      = (const float*)d_in[0];
    const float* hidden = (const float*)d_in[1];
    const float* memory = (const float*)d_in[2];
    const float* Wq     = (const float*)d_in[3];
    const float* Wk     = (const float*)d_in[4];
    const float* Wv     = (const float*)d_in[5];
    const float* iq     = (const float*)d_in[6];
    float* out = (float*)d_out;

    // z=0..2: qkv for expert e=z; z=3: mem (g_mhat)
    prep_kernel<<<dim3(T_ / 128, B_, 4), 128>>>(x, memory, iq, hidden, Wq, Wk, Wv);
    attn_kernel<<<dim3(T_ / TQ_, B_, E_), 128>>>(out);
}

// round 17
// speedup vs baseline: 1.2150x; 1.2150x over previous
#include <cuda_runtime.h>
#include <cuda_bf16.h>
#include <cstdint>

#define B_ 8
#define T_ 2048
#define H_ 64
#define M_ 32
#define S_ 20
#define E_ 3
#define IN_ 32
#define EPS_ 1e-8f
#define LOG2E_ 1.4426950408889634f

#define TQ_ 64           // q rows per CTA
#define TK_ 64           // keys per smem tile
#define NKT_ (T_ / TK_)  // 32

// ---------------- scratch (no cudaMalloc allowed) ----------------
__device__ __align__(16) float g_mhat[B_ * T_ * M_];
// Q,K rows: [hi 32 bf16 | lo 32 bf16] = 32 uints = 128B per row (group-permuted)
__device__ __align__(16) unsigned int g_Qs[E_ * B_ * T_ * 32];
__device__ __align__(16) unsigned int g_Ks[E_ * B_ * T_ * 32];
// V transposed planes: [e][b][m][t/2] bf16 pairs (group-permuted)
__device__ __align__(16) unsigned int g_Vthi[E_ * B_ * 32 * (T_ / 2)];
__device__ __align__(16) unsigned int g_Vtlo[E_ * B_ * 32 * (T_ / 2)];

// ---------------- helpers ----------------
static __device__ __forceinline__ float ex2f(float x) {
    float r; asm("ex2.approx.ftz.f32 %0, %1;" : "=f"(r) : "f"(x)); return r;
}
static __device__ __forceinline__ unsigned short f2bf(float f) {
    __nv_bfloat16 h = __float2bfloat16(f);
    return *reinterpret_cast<unsigned short*>(&h);
}
static __device__ __forceinline__ float bf2f(unsigned short u) {
    __nv_bfloat16 h; *reinterpret_cast<unsigned short*>(&h) = u;
    return __bfloat162float(h);
}
static __device__ __forceinline__ unsigned int pack2(float hi, float lo) {
    unsigned int d;
    asm("cvt.rn.bf16x2.f32 %0, %1, %2;" : "=r"(d) : "f"(hi), "f"(lo));
    return d;
}
static __device__ __forceinline__ float unpk_lo(unsigned int v) { return __uint_as_float(v << 16); }
static __device__ __forceinline__ float unpk_hi(unsigned int v) { return __uint_as_float(v & 0xffff0000u); }

static __device__ __forceinline__ unsigned long long pk2(float a, float b) {
    unsigned long long r;
    asm("mov.b64 %0, {%1, %2};" : "=l"(r) : "r"(__float_as_uint(a)), "r"(__float_as_uint(b)));
    return r;
}
static __device__ __forceinline__ void upk2(unsigned long long v, float& a, float& b) {
    unsigned lo, hi;
    asm("mov.b64 {%0, %1}, %2;" : "=r"(lo), "=r"(hi) : "l"(v));
    a = __uint_as_float(lo); b = __uint_as_float(hi);
}
static __device__ __forceinline__ unsigned long long ffma2(
        unsigned long long a, unsigned long long b, unsigned long long c) {
    unsigned long long d;
    asm("fma.rn.f32x2 %0, %1, %2, %3;" : "=l"(d) : "l"(a), "l"(b), "l"(c));
    return d;
}

static __device__ __forceinline__ void mma16816(
        float* c, unsigned int a0, unsigned int a1, unsigned int a2, unsigned int a3,
        unsigned int b0, unsigned int b1) {
    asm volatile(
        "mma.sync.aligned.m16n8k16.row.col.f32.bf16.bf16.f32 "
        "{%0,%1,%2,%3}, {%4,%5,%6,%7}, {%8,%9}, {%0,%1,%2,%3};"
        : "+f"(c[0]), "+f"(c[1]), "+f"(c[2]), "+f"(c[3])
        : "r"(a0), "r"(a1), "r"(a2), "r"(a3), "r"(b0), "r"(b1));
}

static __device__ __forceinline__ uint32_t smem_u32(const void* p) {
    uint32_t a;
    asm("{ .reg .u64 t; cvta.to.shared.u64 t, %1; cvt.u32.u64 %0, t; }" : "=r"(a) : "l"(p));
    return a;
}
static __device__ __forceinline__ void cpa16(uint32_t s, const void* g) {
    asm volatile("cp.async.cg.shared.global [%0], [%1], 16;" :: "r"(s), "l"(g));
}
#define CPA_COMMIT() asm volatile("cp.async.commit_group;" ::: "memory")
#define CPA_WAIT0()  asm volatile("cp.async.wait_group 0;" ::: "memory")

// group-of-8 word permutation: input word i -> position 2*(i&3) + (i>>2).
// Makes fragment word pairs (i, i+4) adjacent -> LDS.64 in attn.
static __device__ __forceinline__ int perm8(int i) { return ((i & 3) << 1) | (i >> 2); }

// ---------------- prep kernel: qkv (z=0..2) + mem (z=3) ----------------
static __device__ __forceinline__ void split_pack_row(const float* a, unsigned int* dst) {
#pragma unroll
    for (int i = 0; i < 16; i++) {
        int pos = (i & 8) + perm8(i & 7);
        unsigned short h0 = f2bf(a[2 * i]), h1 = f2bf(a[2 * i + 1]);
        dst[pos] = (unsigned)h0 | ((unsigned)h1 << 16);
        float l0 = a[2 * i] - bf2f(h0), l1 = a[2 * i + 1] - bf2f(h1);
        dst[16 + pos] = (unsigned)f2bf(l0) | ((unsigned)f2bf(l1) << 16);
    }
}

__global__ __launch_bounds__(128) void prep_kernel(
        const float* __restrict__ x,
        const float* __restrict__ memory,
        const float* __restrict__ iq,
        const float* __restrict__ hidden,
        const float* __restrict__ Wq,
        const float* __restrict__ Wk,
        const float* __restrict__ Wv) {
    __shared__ unsigned long long w2[3][H_ * 16];   // qkv: packed weight pairs (24KB)
    __shared__ float sv[128 * 32];                  // qkv: V rows for transpose (16KB)
    int tid = threadIdx.x;

    if (blockIdx.z == 3) {
        // ================= mem path: thread per (b,t) row =================
        float* iqs = (float*)w2[0];                // IN*M floats
        float* smem_m = (float*)w2[0] + IN_ * M_;  // S*M floats
        for (int n = tid; n < IN_ * M_; n += 128) iqs[n] = iq[n];
        for (int n = tid; n < S_ * M_; n += 128) smem_m[n] = memory[n];
        __syncthreads();

        int bt = (blockIdx.y * 16 + blockIdx.x) * 128 + tid;   // 0..16383
        float xr[IN_];
        const float4* x4 = (const float4*)(x + (size_t)bt * IN_);
#pragma unroll
        for (int i = 0; i < IN_ / 4; i++) {
            float4 v = x4[i];
            xr[4 * i] = v.x; xr[4 * i + 1] = v.y; xr[4 * i + 2] = v.z; xr[4 * i + 3] = v.w;
        }
        float qv[M_];
#pragma unroll
        for (int m = 0; m < M_; m++) qv[m] = 0.f;
#pragma unroll
        for (int i = 0; i < IN_; i++) {
            float xv = xr[i];
#pragma unroll
            for (int m = 0; m < M_; m++) qv[m] = fmaf(xv, iqs[i * M_ + m], qv[m]);
        }
        float s[S_];
        float mx = -3e38f;
#pragma unroll
        for (int j = 0; j < S_; j++) {
            float d0 = 0.f, d1 = 0.f, d2 = 0.f, d3 = 0.f;
            const float* r = smem_m + j * M_;
#pragma unroll
            for (int m = 0; m < M_; m += 4) {
                d0 = fmaf(qv[m], r[m], d0);
                d1 = fmaf(qv[m + 1], r[m + 1], d1);
                d2 = fmaf(qv[m + 2], r[m + 2], d2);
                d3 = fmaf(qv[m + 3], r[m + 3], d3);
            }
            s[j] = (d0 + d1) + (d2 + d3);
            mx = fmaxf(mx, s[j]);
        }
        float L = 0.f;
#pragma unroll
        for (int j = 0; j < S_; j++) {
            s[j] = ex2f((s[j] - mx) * LOG2E_);
            L += s[j];
        }
        float macc[M_];
#pragma unroll
        for (int m = 0; m < M_; m++) macc[m] = 0.f;
#pragma unroll
        for (int j = 0; j < S_; j++) {
            float p = s[j];
            const float* r = smem_m + j * M_;
#pragma unroll
            for (int m = 0; m < M_; m++) macc[m] = fmaf(p, r[m], macc[m]);
        }
        float invL = 1.0f / L;
        float ss = 0.f;
#pragma unroll
        for (int m = 0; m < M_; m++) {
            macc[m] *= invL;
            ss += macc[m] * macc[m];
        }
        float rinv = 1.0f / fmaxf(sqrtf(ss), EPS_);
        float4* o4 = (float4*)(g_mhat + (size_t)bt * M_);
#pragma unroll
        for (int i = 0; i < M_ / 4; i++) {
            float4 v;
            v.x = macc[4 * i] * rinv; v.y = macc[4 * i + 1] * rinv;
            v.z = macc[4 * i + 2] * rinv; v.w = macc[4 * i + 3] * rinv;
            o4[i] = v;
        }
        return;
    }

    // ================= qkv path =================
    int e = blockIdx.z, b = blockIdx.y;
    const float* Ws[3] = {Wq, Wk, Wv};
    for (int p = 0; p < 3; p++) {
        const unsigned long long* src = (const unsigned long long*)(Ws[p] + e * H_ * M_);
        for (int n = tid; n < H_ * 16; n += 128) w2[p][n] = src[n];
    }
    __syncthreads();

    int t0 = blockIdx.x * 128;
    int t = t0 + tid;
    size_t row = (size_t)(e * B_ + b) * T_ + t;
    float h[H_];
    const float4* h4 = (const float4*)(hidden + row * H_);
#pragma unroll
    for (int i = 0; i < H_ / 4; i++) {
        float4 v = h4[i];
        h[4 * i] = v.x; h[4 * i + 1] = v.y; h[4 * i + 2] = v.z; h[4 * i + 3] = v.w;
    }
    for (int p = 0; p < 3; p++) {
        unsigned long long acc2[16];
#pragma unroll
        for (int m = 0; m < 16; m++) acc2[m] = 0ull;
#pragma unroll
        for (int i = 0; i < H_; i++) {
            unsigned long long h2 = pk2(h[i], h[i]);
#pragma unroll
            for (int m = 0; m < 16; m++)
                acc2[m] = ffma2(h2, w2[p][i * 16 + m], acc2[m]);
        }
        float acc[M_];
#pragma unroll
        for (int m = 0; m < 16; m++) upk2(acc2[m], acc[2 * m], acc[2 * m + 1]);

        if (p == 0) {
#pragma unroll
            for (int m = 0; m < M_; m++) acc[m] *= LOG2E_;   // log2-domain scores
            unsigned int pk[32];
            split_pack_row(acc, pk);
            uint4* o = (uint4*)(g_Qs + row * 32);
#pragma unroll
            for (int i = 0; i < 8; i++) o[i] = ((uint4*)pk)[i];
        } else if (p == 1) {
            unsigned int pk[32];
            split_pack_row(acc, pk);
            uint4* o = (uint4*)(g_Ks + row * 32);
#pragma unroll
            for (int i = 0; i < 8; i++) o[i] = ((uint4*)pk)[i];
        } else {
#pragma unroll
            for (int m = 0; m < M_; m++) sv[tid * 32 + m] = acc[m];
        }
    }
    __syncthreads();
    // transpose V: thread owns (m, t-chunk of 32); write group-permuted words
    int m = tid & 31, tc = tid >> 5;
    size_t vbase = ((size_t)(e * B_ + b) * 32 + m) * (T_ / 2) + (size_t)(t0 + tc * 32) / 2;
#pragma unroll
    for (int j = 0; j < 16; j++) {
        int pos = (j & 8) + perm8(j & 7);
        float f0 = sv[(tc * 32 + 2 * j) * 32 + m];
        float f1 = sv[(tc * 32 + 2 * j + 1) * 32 + m];
        unsigned short h0 = f2bf(f0), h1 = f2bf(f1);
        g_Vthi[vbase + pos] = (unsigned)h0 | ((unsigned)h1 << 16);
        float l0 = f0 - bf2f(h0), l1 = f1 - bf2f(h1);
        g_Vtlo[vbase + pos] = (unsigned)f2bf(l0) | ((unsigned)f2bf(l1) << 16);
    }
}

// ---------------- kernel C: HMMA flash attention + fused cosine ----------------
#define KST_ 160
#define VST_ 160

__global__ __launch_bounds__(128, 4) void attn_kernel(float* __restrict__ out) {
    __shared__ __align__(16) char Qsm[TQ_ * 128];          // 8KB
    __shared__ __align__(16) char Ksm[2][TK_ * KST_];      // 20KB
    __shared__ __align__(16) char Vhism[2][32 * VST_];     // 10KB
    __shared__ __align__(16) char Vlosm[2][32 * VST_];     // 10KB

    int tid = threadIdx.x, wid = tid >> 5, lane = tid & 31;
    int e = blockIdx.z, b = blockIdx.y;
    int qbase = blockIdx.x * TQ_;
    size_t eb = (size_t)(e * B_ + b);
    int lq = lane >> 2;      // 0..7
    int lr = lane & 3;       // 0..3

    const uint4* kg = (const uint4*)g_Ks + eb * T_ * 8;
    const uint4* vhg = (const uint4*)g_Vthi + eb * 32 * 256;
    const uint4* vlg = (const uint4*)g_Vtlo + eb * 32 * 256;

    uint32_t ksb[2] = {smem_u32(Ksm[0]), smem_u32(Ksm[1])};
    uint32_t vhb[2] = {smem_u32(Vhism[0]), smem_u32(Vhism[1])};
    uint32_t vlb[2] = {smem_u32(Vlosm[0]), smem_u32(Vlosm[1])};

    // ---- prefetch tile 0 via cp.async ----
    {
#pragma unroll
        for (int j = 0; j < 4; j++) {
            int i = tid + j * 128;
            int r = i >> 3, ch = i & 7;
            cpa16(ksb[0] + r * KST_ + ch * 16, kg + (size_t)r * 8 + ch);
        }
#pragma unroll
        for (int j = 0; j < 2; j++) {
            int i = tid + j * 128;
            int m = i >> 3, ch = i & 7;
            cpa16(vhb[0] + m * VST_ + ch * 16, vhg + (size_t)m * 256 + ch);
            cpa16(vlb[0] + m * VST_ + ch * 16, vlg + (size_t)m * 256 + ch);
        }
        CPA_COMMIT();
    }

    // ---- load Q tile (plain) ----
    {
        const uint4* qg = (const uint4*)g_Qs + (eb * T_ + qbase) * 8;
#pragma unroll
        for (int j = 0; j < 4; j++) {
            int i = tid + j * 128;
            int r = i >> 3, ch = i & 7;
            *(uint4*)(Qsm + r * 128 + ch * 16) = qg[(size_t)r * 8 + ch];
        }
    }
    __syncthreads();

    // ---- persistent Q A-fragments (pairs adjacent after perm) ----
    unsigned int qhi[2][4], qlo[2][4];
    {
        int r0 = wid * 16 + lq;
#pragma unroll
        for (int kc = 0; kc < 2; kc++) {
            int off = kc * 32 + lr * 8;
            uint2 v0 = *(const uint2*)(Qsm + r0 * 128 + off);
            uint2 v1 = *(const uint2*)(Qsm + (r0 + 8) * 128 + off);
            qhi[kc][0] = v0.x; qhi[kc][1] = v1.x; qhi[kc][2] = v0.y; qhi[kc][3] = v1.y;
            uint2 w0 = *(const uint2*)(Qsm + r0 * 128 + 64 + off);
            uint2 w1 = *(const uint2*)(Qsm + (r0 + 8) * 128 + 64 + off);
            qlo[kc][0] = w0.x; qlo[kc][1] = w1.x; qlo[kc][2] = w0.y; qlo[kc][3] = w1.y;
        }
    }

    float o[4][4];
#pragma unroll
    for (int i = 0; i < 4; i++)
#pragma unroll
        for (int j = 0; j < 4; j++) o[i][j] = 0.f;
    float m0 = -1e30f, m1 = -1e30f;

    for (int kt = 0; kt < NKT_; kt++) {
        int st = kt & 1;
        CPA_WAIT0();
        __syncthreads();
        // ---- prefetch next tile into other buffer ----
        if (kt + 1 < NKT_) {
            int ns = st ^ 1;
            int nk = kt + 1;
#pragma unroll
            for (int j = 0; j < 4; j++) {
                int i = tid + j * 128;
                int r = i >> 3, ch = i & 7;
                cpa16(ksb[ns] + r * KST_ + ch * 16, kg + (size_t)(nk * TK_ + r) * 8 + ch);
            }
#pragma unroll
            for (int j = 0; j < 2; j++) {
                int i = tid + j * 128;
                int m = i >> 3, ch = i & 7;
                cpa16(vhb[ns] + m * VST_ + ch * 16, vhg + (size_t)m * 256 + nk * 8 + ch);
                cpa16(vlb[ns] + m * VST_ + ch * 16, vlg + (size_t)m * 256 + nk * 8 + ch);
            }
            CPA_COMMIT();
        }

        // ---- S = Q K^T (split bf16, 3 passes) ----
        float sc[8][4];
#pragma unroll
        for (int n = 0; n < 8; n++) {
            sc[n][0] = sc[n][1] = sc[n][2] = sc[n][3] = 0.f;
            const char* rowp = Ksm[st] + (n * 8 + lq) * KST_;
#pragma unroll
            for (int kc = 0; kc < 2; kc++) {
                int off = kc * 32 + lr * 8;
                uint2 bh = *(const uint2*)(rowp + off);
                uint2 bl = *(const uint2*)(rowp + 64 + off);
                mma16816(sc[n], qhi[kc][0], qhi[kc][1], qhi[kc][2], qhi[kc][3], bh.x, bh.y);
                mma16816(sc[n], qlo[kc][0], qlo[kc][1], qlo[kc][2], qlo[kc][3], bh.x, bh.y);
                mma16816(sc[n], qhi[kc][0], qhi[kc][1], qhi[kc][2], qhi[kc][3], bl.x, bl.y);
            }
        }

        // ---- online max (log2 domain); rescale only when a row max advances ----
        float mt0 = -1e30f, mt1 = -1e30f;
#pragma unroll
        for (int n = 0; n < 8; n++) {
            mt0 = fmaxf(mt0, fmaxf(sc[n][0], sc[n][1]));
            mt1 = fmaxf(mt1, fmaxf(sc[n][2], sc[n][3]));
        }
        mt0 = fmaxf(mt0, __shfl_xor_sync(0xffffffffu, mt0, 1));
        mt0 = fmaxf(mt0, __shfl_xor_sync(0xffffffffu, mt0, 2));
        mt1 = fmaxf(mt1, __shfl_xor_sync(0xffffffffu, mt1, 1));
        mt1 = fmaxf(mt1, __shfl_xor_sync(0xffffffffu, mt1, 2));
        if (__any_sync(0xffffffffu, (mt0 > m0) || (mt1 > m1))) {
            float mn0 = fmaxf(m0, mt0), mn1 = fmaxf(m1, mt1);
            float s0 = ex2f(m0 - mn0), s1 = ex2f(m1 - mn1);
            m0 = mn0; m1 = mn1;
#pragma unroll
            for (int nv = 0; nv < 4; nv++) {
                o[nv][0] *= s0; o[nv][1] *= s0;
                o[nv][2] *= s1; o[nv][3] *= s1;
            }
        }

        // ---- P = ex2(S-m) -> A-frags; O += P V (split, 3 passes) ----
#pragma unroll
        for (int kc = 0; kc < 4; kc++) {
            float p00 = ex2f(sc[2 * kc][0] - m0), p01 = ex2f(sc[2 * kc][1] - m0);
            float p02 = ex2f(sc[2 * kc][2] - m1), p03 = ex2f(sc[2 * kc][3] - m1);
            float p10 = ex2f(sc[2 * kc + 1][0] - m0), p11 = ex2f(sc[2 * kc + 1][1] - m0);
            float p12 = ex2f(sc[2 * kc + 1][2] - m1), p13 = ex2f(sc[2 * kc + 1][3] - m1);
            unsigned int a0 = pack2(p01, p00);
            unsigned int a1 = pack2(p03, p02);
            unsigned int a2 = pack2(p11, p10);
            unsigned int a3 = pack2(p13, p12);
            unsigned int a0l = pack2(p01 - unpk_hi(a0), p00 - unpk_lo(a0));
            unsigned int a1l = pack2(p03 - unpk_hi(a1), p02 - unpk_lo(a1));
            unsigned int a2l = pack2(p11 - unpk_hi(a2), p10 - unpk_lo(a2));
            unsigned int a3l = pack2(p13 - unpk_hi(a3), p12 - unpk_lo(a3));
#pragma unroll
            for (int nv = 0; nv < 4; nv++) {
                const char* vrow_h = Vhism[st] + (nv * 8 + lq) * VST_;
                const char* vrow_l = Vlosm[st] + (nv * 8 + lq) * VST_;
                int off = kc * 32 + lr * 8;
                uint2 bh = *(const uint2*)(vrow_h + off);
                uint2 bl = *(const uint2*)(vrow_l + off);
                mma16816(o[nv], a0, a1, a2, a3, bh.x, bh.y);
                mma16816(o[nv], a0l, a1l, a2l, a3l, bh.x, bh.y);
                mma16816(o[nv], a0, a1, a2, a3, bl.x, bl.y);
            }
        }
    }

    // ---- epilogue: cosine(o_row, mhat_row); softmax 1/l cancels in cosine ----
    int trow0 = qbase + wid * 16 + lq;
    int trow1 = trow0 + 8;
    float n20 = 0.f, dt0 = 0.f, n21 = 0.f, dt1 = 0.f;
    const float* mh0 = g_mhat + ((size_t)b * T_ + trow0) * M_;
    const float* mh1 = g_mhat + ((size_t)b * T_ + trow1) * M_;
#pragma unroll
    for (int nv = 0; nv < 4; nv++) {
        int col = nv * 8 + lr * 2;
        float2 w0 = *(const float2*)(mh0 + col);
        float2 w1 = *(const float2*)(mh1 + col);
        n20 += o[nv][0] * o[nv][0] + o[nv][1] * o[nv][1];
        dt0 += o[nv][0] * w0.x + o[nv][1] * w0.y;
        n21 += o[nv][2] * o[nv][2] + o[nv][3] * o[nv][3];
        dt1 += o[nv][2] * w1.x + o[nv][3] * w1.y;
    }
    n20 += __shfl_xor_sync(0xffffffffu, n20, 1);
    dt0 += __shfl_xor_sync(0xffffffffu, dt0, 1);
    n21 += __shfl_xor_sync(0xffffffffu, n21, 1);
    dt1 += __shfl_xor_sync(0xffffffffu, dt1, 1);
    n20 += __shfl_xor_sync(0xffffffffu, n20, 2);
    dt0 += __shfl_xor_sync(0xffffffffu, dt0, 2);
    n21 += __shfl_xor_sync(0xffffffffu, n21, 2);
    dt1 += __shfl_xor_sync(0xffffffffu, dt1, 2);
    if (lr == 0) {
        out[((size_t)b * T_ + trow0) * E_ + e] = dt0 / fmaxf(sqrtf(n20), EPS_);
        out[((size_t)b * T_ + trow1) * E_ + e] = dt1 / fmaxf(sqrtf(n21), EPS_);
    }
}

// ---------------- launch ----------------
extern "C" void kernel_launch(void* const* d_in, const int* in_sizes, int n_in,
                              void* d_out, int out_size) {
    const float* x      = (const float*)d_in[0];
    const float* hidden = (const float*)d_in[1];
    const float* memory = (const float*)d_in[2];
    const float* Wq     = (const float*)d_in[3];
    const float* Wk     = (const float*)d_in[4];
    const float* Wv     = (const float*)d_in[5];
    const float* iq     = (const float*)d_in[6];
    float* out = (float*)d_out;

    // z=0..2: qkv for expert e=z; z=3: mem (g_mhat)
    prep_kernel<<<dim3(T_ / 128, B_, 4), 128>>>(x, memory, iq, hidden, Wq, Wk, Wv);
    attn_kernel<<<dim3(T_ / TQ_, B_, E_), 128>>>(out);
}